// round 3
// baseline (speedup 1.0000x reference)
#include <cuda_runtime.h>
#include <math.h>
#include <stdint.h>

#define PRIMEY 2654435761u

struct Res8 { float rx[8]; float ry[8]; };

__device__ __forceinline__ float4 exp4(float4 v) {
    return make_float4(__expf(v.x), __expf(v.y), __expf(v.z), __expf(v.w));
}
__device__ __forceinline__ float sigm1(float v) { return 1.0f / (1.0f + __expf(-v)); }
__device__ __forceinline__ float4 sig4(float4 v) {
    return make_float4(sigm1(v.x), sigm1(v.y), sigm1(v.z), sigm1(v.w));
}

__global__ void __launch_bounds__(256) pg_kernel(
    const float2* __restrict__ xs,
    const int*    __restrict__ hashidxs,
    const float*  __restrict__ table,
    const float4* __restrict__ w1v,   // 16*32 floats = 128 float4
    const float4* __restrict__ b1v,   // 32 floats = 8 float4
    const float4* __restrict__ w2v,   // 32*24 floats = 192 float4
    const float4* __restrict__ b2v,   // 24 floats = 6 float4
    float4*       __restrict__ out4,
    int n, Res8 rr)
{
    __shared__ float4 s_w1[128];
    __shared__ float4 s_w2[192];
    __shared__ float4 s_b1[8];
    __shared__ float4 s_b2[6];
    {
        int t = threadIdx.x;
        if (t < 128) s_w1[t] = w1v[t];
        for (int k = t; k < 192; k += 256) s_w2[k] = w2v[k];
        if (t < 8) s_b1[t] = b1v[t];
        if (t < 6) s_b2[t] = b2v[t];
    }
    __syncthreads();

    int p = blockIdx.x * 256 + threadIdx.x;
    if (p >= n) return;

    float2 xp = xs[p];
    const float2* tb = (const float2*)table + (size_t)hashidxs[p] * (8u * 16384u);

    float H[16];
#pragma unroll
    for (int l = 0; l < 8; l++) {
        float px = xp.x * rr.rx[l];
        float py = xp.y * rr.ry[l];
        float fx = floorf(px), fy = floorf(py);
        float wx = px - fx,    wy = py - fy;
        unsigned xi = (unsigned)fx, yi = (unsigned)fy;
        unsigned hy0 = yi * PRIMEY;
        unsigned hy1 = hy0 + PRIMEY;     // (yi+1)*PRIMEY mod 2^32
        const float2* tl = tb + l * 16384;
        float2 f00 = __ldg(tl + ((xi        ^ hy0) & 16383u));
        float2 f10 = __ldg(tl + (((xi + 1u) ^ hy0) & 16383u));
        float2 f01 = __ldg(tl + ((xi        ^ hy1) & 16383u));
        float2 f11 = __ldg(tl + (((xi + 1u) ^ hy1) & 16383u));
        float w00 = (1.f - wx) * (1.f - wy);
        float w10 = wx * (1.f - wy);
        float w01 = (1.f - wx) * wy;
        float w11 = wx * wy;
        H[2 * l]     = f00.x * w00 + f10.x * w10 + f01.x * w01 + f11.x * w11;
        H[2 * l + 1] = f00.y * w00 + f10.y * w10 + f01.y * w01 + f11.y * w11;
    }

    // Layer 1: h1[32] = H[16] @ w1[16,32] + b1, then gaussian activation
    float4 h1[8];
#pragma unroll
    for (int j = 0; j < 8; j++) h1[j] = s_b1[j];
#pragma unroll
    for (int i = 0; i < 16; i++) {
        float hi = H[i];
#pragma unroll
        for (int j = 0; j < 8; j++) {
            float4 w = s_w1[i * 8 + j];
            h1[j].x = fmaf(hi, w.x, h1[j].x);
            h1[j].y = fmaf(hi, w.y, h1[j].y);
            h1[j].z = fmaf(hi, w.z, h1[j].z);
            h1[j].w = fmaf(hi, w.w, h1[j].w);
        }
    }
#pragma unroll
    for (int j = 0; j < 8; j++) {
        h1[j].x = __expf(h1[j].x * h1[j].x * -50.f);
        h1[j].y = __expf(h1[j].y * h1[j].y * -50.f);
        h1[j].z = __expf(h1[j].z * h1[j].z * -50.f);
        h1[j].w = __expf(h1[j].w * h1[j].w * -50.f);
    }

    // Layer 2: raw[24] = h1[32] @ w2[32,24] + b2
    float4 raw[6];
#pragma unroll
    for (int o = 0; o < 6; o++) raw[o] = s_b2[o];
#pragma unroll
    for (int j = 0; j < 8; j++) {
        float hv4[4] = {h1[j].x, h1[j].y, h1[j].z, h1[j].w};
#pragma unroll
        for (int c = 0; c < 4; c++) {
            float ht = hv4[c];
            int t = j * 4 + c;
#pragma unroll
            for (int o = 0; o < 6; o++) {
                float4 w = s_w2[t * 6 + o];
                raw[o].x = fmaf(ht, w.x, raw[o].x);
                raw[o].y = fmaf(ht, w.y, raw[o].y);
                raw[o].z = fmaf(ht, w.z, raw[o].z);
                raw[o].w = fmaf(ht, w.w, raw[o].w);
            }
        }
    }

    // Epilogue: weight = exp(raw[0:8]); mu = sigmoid(raw[8:16]); inv_sigma = exp(raw[16:24])
    float4 wt0 = exp4(raw[0]), wt1 = exp4(raw[1]);
    float4 mu0 = sig4(raw[2]), mu1 = sig4(raw[3]);
    float4 is0 = exp4(raw[4]), is1 = exp4(raw[5]);

    // Output layout (float4 units): mu | inv_sigma | weight | H
    size_t n2 = (size_t)n * 2;
    float4* mup = out4;
    float4* isp = out4 + n2;
    float4* wtp = out4 + 2 * n2;
    float4* Hp  = out4 + 3 * n2;
    size_t p2 = (size_t)p * 2;
    mup[p2]     = mu0; mup[p2 + 1] = mu1;
    isp[p2]     = is0; isp[p2 + 1] = is1;
    wtp[p2]     = wt0; wtp[p2 + 1] = wt1;
    size_t p4 = (size_t)p * 4;
    Hp[p4 + 0] = make_float4(H[0],  H[1],  H[2],  H[3]);
    Hp[p4 + 1] = make_float4(H[4],  H[5],  H[6],  H[7]);
    Hp[p4 + 2] = make_float4(H[8],  H[9],  H[10], H[11]);
    Hp[p4 + 3] = make_float4(H[12], H[13], H[14], H[15]);
}

extern "C" void kernel_launch(void* const* d_in, const int* in_sizes, int n_in,
                              void* d_out, int out_size) {
    const float2* x     = (const float2*)d_in[0];
    const int*    hidx  = (const int*)d_in[1];
    // d_in[2] = color (unused by reference outputs)
    const float*  table = (const float*)d_in[3];
    const float4* w1    = (const float4*)d_in[4];
    const float4* b1    = (const float4*)d_in[5];
    const float4* w2    = (const float4*)d_in[6];
    const float4* b2    = (const float4*)d_in[7];
    int n = in_sizes[1];

    // Mirror reference _level_resolutions() in double precision
    Res8 rr;
    double bx = exp((log(1024.0) - log(16.0)) / 7.0);
    double by = exp((log(768.0)  - log(16.0)) / 7.0);
    for (int l = 0; l < 8; l++) {
        rr.rx[l] = (float)floor(16.0 * pow(bx, (double)l));
        rr.ry[l] = (float)floor(16.0 * pow(by, (double)l));
    }

    int blocks = (n + 255) / 256;
    pg_kernel<<<blocks, 256>>>(x, hidx, table, w1, b1, w2, b2, (float4*)d_out, n, rr);
}

// round 5
// speedup vs baseline: 1.1911x; 1.1911x over previous
#include <cuda_runtime.h>
#include <math.h>
#include <stdint.h>

#define PRIMEY 2654435761u

struct Res8 { float rx[8]; float ry[8]; };

__constant__ float4 c_w1[128];  // w1[16][32]
__constant__ float4 c_b1[8];    // b1[32]
__constant__ float4 c_w2[192];  // w2[32][24]
__constant__ float4 c_b2[6];    // b2[24]

__device__ __forceinline__ float4 exp4(float4 v) {
    return make_float4(__expf(v.x), __expf(v.y), __expf(v.z), __expf(v.w));
}
__device__ __forceinline__ float sigm1(float v) { return 1.0f / (1.0f + __expf(-v)); }
__device__ __forceinline__ float4 sig4(float4 v) {
    return make_float4(sigm1(v.x), sigm1(v.y), sigm1(v.z), sigm1(v.w));
}

__global__ void __launch_bounds__(256) pg_kernel(
    const float2* __restrict__ xs,
    const int*    __restrict__ hashidxs,
    const float*  __restrict__ table,
    float4*       __restrict__ out4,
    int n, Res8 rr)
{
    int p = blockIdx.x * 256 + threadIdx.x;
    if (p >= n) return;

    float2 xp = __ldg(xs + p);
    const float2* tb = (const float2*)table + (size_t)__ldg(hashidxs + p) * (8u * 16384u);

    float H[16];
#pragma unroll
    for (int l = 0; l < 8; l++) {
        float px = xp.x * rr.rx[l];
        float py = xp.y * rr.ry[l];
        float fx = floorf(px), fy = floorf(py);
        float wx = px - fx,    wy = py - fy;
        unsigned xi = (unsigned)fx, yi = (unsigned)fy;
        unsigned hy0 = yi * PRIMEY;
        unsigned hy1 = hy0 + PRIMEY;     // (yi+1)*PRIMEY mod 2^32
        const float2* tl = tb + l * 16384;
        const float4* tl4 = (const float4*)tl;
        bool xodd = (xi & 1u) != 0u;

        // Row y0: aligned pair containing idx00; conditional extra load if xi odd
        unsigned i00 = (xi        ^ hy0) & 16383u;
        unsigned i10 = ((xi + 1u) ^ hy0) & 16383u;
        float4 q0 = __ldg(tl4 + (i00 >> 1));
        bool hi0 = (i00 & 1u) != 0u;
        float2 f00 = hi0 ? make_float2(q0.z, q0.w) : make_float2(q0.x, q0.y);
        float2 o0  = hi0 ? make_float2(q0.x, q0.y) : make_float2(q0.z, q0.w);
        float2 f10;
        if (xodd) f10 = __ldg(tl + i10); else f10 = o0;

        // Row y1
        unsigned i01 = (xi        ^ hy1) & 16383u;
        unsigned i11 = ((xi + 1u) ^ hy1) & 16383u;
        float4 q1 = __ldg(tl4 + (i01 >> 1));
        bool hi1 = (i01 & 1u) != 0u;
        float2 f01 = hi1 ? make_float2(q1.z, q1.w) : make_float2(q1.x, q1.y);
        float2 o1  = hi1 ? make_float2(q1.x, q1.y) : make_float2(q1.z, q1.w);
        float2 f11;
        if (xodd) f11 = __ldg(tl + i11); else f11 = o1;

        float w00 = (1.f - wx) * (1.f - wy);
        float w10 = wx * (1.f - wy);
        float w01 = (1.f - wx) * wy;
        float w11 = wx * wy;
        H[2 * l]     = f00.x * w00 + f10.x * w10 + f01.x * w01 + f11.x * w11;
        H[2 * l + 1] = f00.y * w00 + f10.y * w10 + f01.y * w01 + f11.y * w11;
    }

    // Layer 1: h1[32] = H[16] @ w1[16,32] + b1, then gaussian activation
    float4 h1[8];
#pragma unroll
    for (int j = 0; j < 8; j++) h1[j] = c_b1[j];
#pragma unroll
    for (int i = 0; i < 16; i++) {
        float hi = H[i];
#pragma unroll
        for (int j = 0; j < 8; j++) {
            float4 w = c_w1[i * 8 + j];
            h1[j].x = fmaf(hi, w.x, h1[j].x);
            h1[j].y = fmaf(hi, w.y, h1[j].y);
            h1[j].z = fmaf(hi, w.z, h1[j].z);
            h1[j].w = fmaf(hi, w.w, h1[j].w);
        }
    }
#pragma unroll
    for (int j = 0; j < 8; j++) {
        h1[j].x = __expf(h1[j].x * h1[j].x * -50.f);
        h1[j].y = __expf(h1[j].y * h1[j].y * -50.f);
        h1[j].z = __expf(h1[j].z * h1[j].z * -50.f);
        h1[j].w = __expf(h1[j].w * h1[j].w * -50.f);
    }

    // Layer 2: raw[24] = h1[32] @ w2[32,24] + b2
    float4 raw[6];
#pragma unroll
    for (int o = 0; o < 6; o++) raw[o] = c_b2[o];
#pragma unroll
    for (int j = 0; j < 8; j++) {
        float hv4[4] = {h1[j].x, h1[j].y, h1[j].z, h1[j].w};
#pragma unroll
        for (int c = 0; c < 4; c++) {
            float ht = hv4[c];
            int t = j * 4 + c;
#pragma unroll
            for (int o = 0; o < 6; o++) {
                float4 w = c_w2[t * 6 + o];
                raw[o].x = fmaf(ht, w.x, raw[o].x);
                raw[o].y = fmaf(ht, w.y, raw[o].y);
                raw[o].z = fmaf(ht, w.z, raw[o].z);
                raw[o].w = fmaf(ht, w.w, raw[o].w);
            }
        }
    }

    // Epilogue: weight = exp(raw[0:8]); mu = sigmoid(raw[8:16]); inv_sigma = exp(raw[16:24])
    float4 wt0 = exp4(raw[0]), wt1 = exp4(raw[1]);
    float4 mu0 = sig4(raw[2]), mu1 = sig4(raw[3]);
    float4 is0 = exp4(raw[4]), is1 = exp4(raw[5]);

    // Output layout (float4 units): mu | inv_sigma | weight | H
    size_t n2 = (size_t)n * 2;
    float4* mup = out4;
    float4* isp = out4 + n2;
    float4* wtp = out4 + 2 * n2;
    float4* Hp  = out4 + 3 * n2;
    size_t p2 = (size_t)p * 2;
    mup[p2]     = mu0; mup[p2 + 1] = mu1;
    isp[p2]     = is0; isp[p2 + 1] = is1;
    wtp[p2]     = wt0; wtp[p2 + 1] = wt1;
    size_t p4 = (size_t)p * 4;
    Hp[p4 + 0] = make_float4(H[0],  H[1],  H[2],  H[3]);
    Hp[p4 + 1] = make_float4(H[4],  H[5],  H[6],  H[7]);
    Hp[p4 + 2] = make_float4(H[8],  H[9],  H[10], H[11]);
    Hp[p4 + 3] = make_float4(H[12], H[13], H[14], H[15]);
}

extern "C" void kernel_launch(void* const* d_in, const int* in_sizes, int n_in,
                              void* d_out, int out_size) {
    const float2* x     = (const float2*)d_in[0];
    const int*    hidx  = (const int*)d_in[1];
    // d_in[2] = color (unused by reference outputs)
    const float*  table = (const float*)d_in[3];
    int n = in_sizes[1];

    // Stage MLP weights into constant memory (async D2D copies; graph-capturable)
    cudaMemcpyToSymbolAsync(c_w1, d_in[4], 16 * 32 * sizeof(float), 0, cudaMemcpyDeviceToDevice, 0);
    cudaMemcpyToSymbolAsync(c_b1, d_in[5], 32 * sizeof(float),      0, cudaMemcpyDeviceToDevice, 0);
    cudaMemcpyToSymbolAsync(c_w2, d_in[6], 32 * 24 * sizeof(float), 0, cudaMemcpyDeviceToDevice, 0);
    cudaMemcpyToSymbolAsync(c_b2, d_in[7], 24 * sizeof(float),      0, cudaMemcpyDeviceToDevice, 0);

    // Mirror reference _level_resolutions() in double precision
    Res8 rr;
    double bx = exp((log(1024.0) - log(16.0)) / 7.0);
    double by = exp((log(768.0)  - log(16.0)) / 7.0);
    for (int l = 0; l < 8; l++) {
        rr.rx[l] = (float)floor(16.0 * pow(bx, (double)l));
        rr.ry[l] = (float)floor(16.0 * pow(by, (double)l));
    }

    int blocks = (n + 255) / 256;
    pg_kernel<<<blocks, 256>>>(x, hidx, table, (float4*)d_out, n, rr);
}